// round 17
// baseline (speedup 1.0000x reference)
#include <cuda_runtime.h>
#include <cuda_fp16.h>
#include <mma.h>
#include <cstdint>
#include <cstddef>

using namespace nvcuda;

#define N_NODES  100000
#define N_EDGES  3200000
#define D_FEAT   256
#define FILTERS  256
#define NBLK     ((N_NODES + 255) / 256)   // 391 scan blocks

// ---- scratch in __device__ globals (no allocations allowed) ----
__device__ float  g_deg[N_NODES];
__device__ float  g_dinv[N_NODES];
__device__ __half g_h[(size_t)N_NODES * FILTERS];  // dinv-scaled projection, fp16, 51.2 MB
__device__ int    g_cnt[N_NODES];
__device__ int    g_scan[N_NODES];
__device__ int    g_part[NBLK];
__device__ int    g_partx[NBLK];
__device__ int    g_rowptr[N_NODES + 1];
__device__ int    g_cursor[N_NODES];
__device__ int2   g_ecv[N_EDGES];                  // packed (col, val bits)
__device__ __half g_wth[D_FEAT * FILTERS];         // w^T hi: [n][k] fp16
__device__ __half g_wtl[D_FEAT * FILTERS];         // w^T lo (residual): [n][k] fp16

// ======================= small kernels =======================
__global__ void zero_kernel() {
    int i = blockIdx.x * blockDim.x + threadIdx.x;
    if (i < N_NODES) { g_deg[i] = 0.0f; g_cnt[i] = 0; }
}

__global__ void hist_kernel(const int* __restrict__ row,
                            const float* __restrict__ vals) {
    int e = blockIdx.x * blockDim.x + threadIdx.x;
    if (e < N_EDGES) {
        int r = row[e];
        atomicAdd(&g_cnt[r], 1);
        atomicAdd(&g_deg[r], vals[e]);
    }
}

__global__ void dinv_kernel() {
    int i = blockIdx.x * blockDim.x + threadIdx.x;
    if (i < N_NODES) {
        float d = g_deg[i];
        g_dinv[i] = d > 0.0f ? rsqrtf(d) : 0.0f;
    }
}

__global__ void scanA_kernel() {
    __shared__ int sh[256];
    int i = blockIdx.x * 256 + threadIdx.x;
    int v = (i < N_NODES) ? g_cnt[i] : 0;
    sh[threadIdx.x] = v;
    __syncthreads();
#pragma unroll
    for (int off = 1; off < 256; off <<= 1) {
        int t = (threadIdx.x >= off) ? sh[threadIdx.x - off] : 0;
        __syncthreads();
        sh[threadIdx.x] += t;
        __syncthreads();
    }
    if (i < N_NODES) g_scan[i] = sh[threadIdx.x];
    if (threadIdx.x == 255) g_part[blockIdx.x] = sh[255];
}

__global__ void scanB_kernel() {
    __shared__ int sh[512];
    int t = threadIdx.x;
    int v = (t < NBLK) ? g_part[t] : 0;
    sh[t] = v;
    __syncthreads();
#pragma unroll
    for (int off = 1; off < 512; off <<= 1) {
        int u = (t >= off) ? sh[t - off] : 0;
        __syncthreads();
        sh[t] += u;
        __syncthreads();
    }
    if (t < NBLK) g_partx[t] = sh[t] - v;
}

__global__ void scanC_kernel() {
    int i = blockIdx.x * 256 + threadIdx.x;
    if (i < N_NODES) {
        int excl = g_scan[i] - g_cnt[i] + g_partx[blockIdx.x];
        g_rowptr[i] = excl;
        g_cursor[i] = excl;
    }
    if (i == 0) g_rowptr[N_NODES] = N_EDGES;
}

__global__ void fill_kernel(const int* __restrict__ row,
                            const int* __restrict__ col,
                            const float* __restrict__ vals) {
    int e = blockIdx.x * blockDim.x + threadIdx.x;
    if (e < N_EDGES) {
        int r = row[e];
        int pos = atomicAdd(&g_cursor[r], 1);
        g_ecv[pos] = make_int2(col[e], __float_as_int(vals[e]));
    }
}

// split w into hi/lo fp16 transposed: g_wth/g_wtl[n][k] = split(w[k][n])
__global__ void wsplit_kernel(const float* __restrict__ W) {
    int idx = blockIdx.x * blockDim.x + threadIdx.x;
    if (idx < D_FEAT * FILTERS) {
        int k = idx >> 8, n = idx & 255;
        float f = W[idx];                      // w[k][n]
        __half h = __float2half_rn(f);
        __half l = __float2half_rn(f - __half2float(h));
        g_wth[n * D_FEAT + k] = h;
        g_wtl[n * D_FEAT + k] = l;
    }
}

// ======================= wmma (HMMA) GEMM =======================
// Per CTA: 64 node rows x 256 filters. 8 warps in 2(m) x 4(n); warp tile 32x64.
// x is loaded fp32 and split hi/lo in-register (fused xsplit).
// D(fp32) = xh*wh + xl*wh + xh*wl  (~fp32 accuracy); epilogue scales by dinv,
// stores fp16 g_h.
#define BMW   64
#define BKW   64
#define LDA   72                       // padded row stride (halves), 144 B (16B-mult)
#define AH_OFF  0
#define AL_OFF  (AH_OFF + BMW * LDA * 2)            // 9216
#define BH_OFF  (AL_OFF + BMW * LDA * 2)            // 18432
#define BL_OFF  (BH_OFF + FILTERS * LDA * 2)        // 55296
#define SCR_OFF (BL_OFF + FILTERS * LDA * 2)        // 92160
#define GEMM_SMEM (SCR_OFF + 8 * 256 * 4)           // + 8KB scratch = 100352

__global__ __launch_bounds__(256) void gemm_wmma_kernel(const float* __restrict__ X) {
    extern __shared__ __align__(16) char smem[];
    __half* Ah = (__half*)(smem + AH_OFF);
    __half* Al = (__half*)(smem + AL_OFF);
    __half* Bh = (__half*)(smem + BH_OFF);
    __half* Bl = (__half*)(smem + BL_OFF);

    const int tid  = threadIdx.x;
    const int wid  = tid >> 5;
    const int lane = tid & 31;
    const int wm   = wid & 1;           // 0..1 -> rows wm*32..+32
    const int wn   = wid >> 1;          // 0..3 -> cols wn*64..+64
    const int tile0 = blockIdx.x * BMW;

    wmma::fragment<wmma::accumulator, 16, 16, 16, float> acc[2][4];
#pragma unroll
    for (int i = 0; i < 2; ++i)
#pragma unroll
        for (int j = 0; j < 4; ++j) wmma::fill_fragment(acc[i][j], 0.0f);

    for (int ch = 0; ch < 4; ++ch) {
        const int k0 = ch * BKW;

        // ---- stage A: load fp32 x, split hi/lo in-register [64 x 64] ----
        // 64*64 floats = 1024 float4; 256 threads x 4 each.
#pragma unroll
        for (int p = 0; p < 4; ++p) {
            int idx = tid + p * 256;          // 0..1023 float4s
            int r = idx >> 4, c4 = idx & 15;  // row, float4-within-row
            int gm = tile0 + r;
            float4 v = make_float4(0.f, 0.f, 0.f, 0.f);
            if (gm < N_NODES)
                v = __ldg((const float4*)(X + (size_t)gm * D_FEAT + k0) + c4);
            __half h[4], l[4];
            h[0] = __float2half_rn(v.x); l[0] = __float2half_rn(v.x - __half2float(h[0]));
            h[1] = __float2half_rn(v.y); l[1] = __float2half_rn(v.y - __half2float(h[1]));
            h[2] = __float2half_rn(v.z); l[2] = __float2half_rn(v.z - __half2float(h[2]));
            h[3] = __float2half_rn(v.w); l[3] = __float2half_rn(v.w - __half2float(h[3]));
            *(int2*)(Ah + r * LDA + c4 * 4) = *(int2*)h;
            *(int2*)(Al + r * LDA + c4 * 4) = *(int2*)l;
        }
        // ---- stage B hi/lo [256 x 64] (wT layout [n][k]) ----
#pragma unroll
        for (int p = 0; p < 8; ++p) {
            int idx = tid + p * 256;          // 0..2047 int4s
            int n = idx >> 3, k8 = idx & 7;
            size_t off = ((size_t)n * D_FEAT + k0 + k8 * 8) >> 3;
            *(int4*)(Bh + n * LDA + k8 * 8) = __ldg((const int4*)g_wth + off);
            *(int4*)(Bl + n * LDA + k8 * 8) = __ldg((const int4*)g_wtl + off);
        }
        __syncthreads();

        // ---- 4 K-steps of 16, 3 terms ----
#pragma unroll
        for (int ks = 0; ks < 4; ++ks) {
            const int kk = ks * 16;
            wmma::fragment<wmma::matrix_a, 16, 16, 16, __half, wmma::row_major> ah[2], al[2];
#pragma unroll
            for (int i = 0; i < 2; ++i) {
                wmma::load_matrix_sync(ah[i], Ah + (wm * 32 + i * 16) * LDA + kk, LDA);
                wmma::load_matrix_sync(al[i], Al + (wm * 32 + i * 16) * LDA + kk, LDA);
            }
#pragma unroll
            for (int j = 0; j < 4; ++j) {
                wmma::fragment<wmma::matrix_b, 16, 16, 16, __half, wmma::col_major> bh, bl;
                wmma::load_matrix_sync(bh, Bh + (wn * 64 + j * 16) * LDA + kk, LDA);
                wmma::load_matrix_sync(bl, Bl + (wn * 64 + j * 16) * LDA + kk, LDA);
#pragma unroll
                for (int i = 0; i < 2; ++i) {
                    wmma::mma_sync(acc[i][j], ah[i], bh, acc[i][j]);
                    wmma::mma_sync(acc[i][j], al[i], bh, acc[i][j]);
                    wmma::mma_sync(acc[i][j], ah[i], bl, acc[i][j]);
                }
            }
        }
        __syncthreads();
    }

    // ---- epilogue: per-warp scratch -> dinv scale -> fp16 g_h ----
    float* scr = (float*)(smem + SCR_OFF) + wid * 256;
    const int r  = lane >> 1;            // 0..15
    const int c8 = (lane & 1) * 8;       // 0 or 8
#pragma unroll
    for (int i = 0; i < 2; ++i) {
#pragma unroll
        for (int j = 0; j < 4; ++j) {
            wmma::store_matrix_sync(scr, acc[i][j], 16, wmma::mem_row_major);
            __syncwarp();
            const int m = tile0 + wm * 32 + i * 16 + r;
            if (m < N_NODES) {
                const float s = g_dinv[m];
                uint32_t u[4];
#pragma unroll
                for (int q = 0; q < 4; ++q) {
                    __half2 h = __floats2half2_rn(scr[r * 16 + c8 + 2 * q] * s,
                                                  scr[r * 16 + c8 + 2 * q + 1] * s);
                    u[q] = *(uint32_t*)&h;
                }
                *(int4*)(g_h + (size_t)m * FILTERS + wn * 64 + j * 16 + c8) =
                    make_int4(u[0], u[1], u[2], u[3]);
            }
            __syncwarp();
        }
    }
}

// ======================= CSR aggregation =======================
// One warp per node; 8-edge unroll for MLP=8; fused dinv/bias/relu epilogue.
__global__ __launch_bounds__(256) void agg_kernel(float* __restrict__ out,
                                                  const float* __restrict__ bias) {
    const int wid  = (blockIdx.x * blockDim.x + threadIdx.x) >> 5;
    const int lane = threadIdx.x & 31;
    if (wid >= N_NODES) return;

    const int start = g_rowptr[wid];
    const int end   = g_rowptr[wid + 1];

    const float4* H = (const float4*)g_h;   // 32 float4 per row (256 halfs)
    float a[8];
#pragma unroll
    for (int j = 0; j < 8; ++j) a[j] = 0.0f;

    int i = start;
    for (; i + 7 < end; i += 8) {
        int2   e[8];
        float4 r[8];
#pragma unroll
        for (int q = 0; q < 8; ++q) e[q] = __ldg(&g_ecv[i + q]);
#pragma unroll
        for (int q = 0; q < 8; ++q) r[q] = __ldg(H + (size_t)e[q].x * 32 + lane);
#pragma unroll
        for (int q = 0; q < 8; ++q) {
            float v = __int_as_float(e[q].y);
            const __half2* p = (const __half2*)&r[q];
#pragma unroll
            for (int j = 0; j < 4; ++j) {
                float2 f = __half22float2(p[j]);
                a[2*j]   = fmaf(v, f.x, a[2*j]);
                a[2*j+1] = fmaf(v, f.y, a[2*j+1]);
            }
        }
    }
    for (; i < end; ++i) {
        int2 e0 = __ldg(&g_ecv[i]);
        float4 r0 = __ldg(H + (size_t)e0.x * 32 + lane);
        float v0 = __int_as_float(e0.y);
        const __half2* p0 = (const __half2*)&r0;
#pragma unroll
        for (int j = 0; j < 4; ++j) {
            float2 f0 = __half22float2(p0[j]);
            a[2*j]   = fmaf(v0, f0.x, a[2*j]);
            a[2*j+1] = fmaf(v0, f0.y, a[2*j+1]);
        }
    }

    const float s = g_dinv[wid];
    const float4* bias4 = (const float4*)bias;
    float4 b0 = __ldg(bias4 + lane * 2);
    float4 b1 = __ldg(bias4 + lane * 2 + 1);

    float4 o0, o1;
    o0.x = fmaxf(fmaf(a[0], s, b0.x), 0.0f);
    o0.y = fmaxf(fmaf(a[1], s, b0.y), 0.0f);
    o0.z = fmaxf(fmaf(a[2], s, b0.z), 0.0f);
    o0.w = fmaxf(fmaf(a[3], s, b0.w), 0.0f);
    o1.x = fmaxf(fmaf(a[4], s, b1.x), 0.0f);
    o1.y = fmaxf(fmaf(a[5], s, b1.y), 0.0f);
    o1.z = fmaxf(fmaf(a[6], s, b1.z), 0.0f);
    o1.w = fmaxf(fmaf(a[7], s, b1.w), 0.0f);

    float4* op = (float4*)(out + (size_t)wid * FILTERS) + lane * 2;
    op[0] = o0;
    op[1] = o1;
}

// ---------------------------------------------------------------
extern "C" void kernel_launch(void* const* d_in, const int* in_sizes, int n_in,
                              void* d_out, int out_size) {
    const float* x        = (const float*)d_in[0];
    const int*   edge_row = (const int*)d_in[1];
    const int*   edge_col = (const int*)d_in[2];
    const float* edge_val = (const float*)d_in[3];
    const float* w        = (const float*)d_in[4];
    const float* b        = (const float*)d_in[5];
    float*       out      = (float*)d_out;

    cudaFuncSetAttribute(gemm_wmma_kernel,
                         cudaFuncAttributeMaxDynamicSharedMemorySize, GEMM_SMEM);

    // 1) counts + weighted degree
    zero_kernel<<<NBLK, 256>>>();
    hist_kernel<<<(N_EDGES + 255) / 256, 256>>>(edge_row, edge_val);
    dinv_kernel<<<NBLK, 256>>>();

    // 2) CSR build: scan + fill
    scanA_kernel<<<NBLK, 256>>>();
    scanB_kernel<<<1, 512>>>();
    scanC_kernel<<<NBLK, 256>>>();
    fill_kernel<<<(N_EDGES + 255) / 256, 256>>>(edge_row, edge_col, edge_val);

    // 3) w split (hi/lo fp16, transposed); x split is fused into the GEMM
    wsplit_kernel<<<(D_FEAT * FILTERS + 255) / 256, 256>>>(w);

    // 4) HMMA GEMM: g_h = (half) dinv * (x @ w), 3-term compensated fp16
    gemm_wmma_kernel<<<(N_NODES + BMW - 1) / BMW, 256, GEMM_SMEM>>>(x);

    // 5) CSR aggregation with fused dinv/bias/relu epilogue
    agg_kernel<<<(N_NODES * 32 + 255) / 256, 256>>>(out, b);
}